// round 11
// baseline (speedup 1.0000x reference)
#include <cuda_runtime.h>

#define DD    32          // embedding dim D
#define MM    32          // memories per hop
#define LEAKY 0.2f

// scratch
__device__ float g_Rh[131072 * 32];    // Rh[slot][d] for hop>=1 slots
__device__ float g_logit0[131072];     // hop-0 logits (slot < B*M)
__device__ int   g_done;               // zero-init; self-resets each launch
__device__ int   g_rdone;

__device__ __forceinline__ float warpSum(float v) {
    #pragma unroll
    for (int off = 16; off; off >>= 1) v += __shfl_xor_sync(0xffffffffu, v, off);
    return v;
}
__device__ __forceinline__ float warpMax(float v) {
    #pragma unroll
    for (int off = 16; off; off >>= 1) v = fmaxf(v, __shfl_xor_sync(0xffffffffu, v, off));
    return v;
}

// ---------------------------------------------------------------------------
// ONE fused kernel. blockIdx ranges, in scheduling order:
//   [0, RB)     r_all gather + fused Rh / hop0-logit       (producer)
//   [+TB)       t_all gather (leaky)                       (producer)
//   [+IB)       iEmbed base copy into out_i                (producer!)
//   [+RP)       ripple hops + scatter — waits on ALL producers, then runs
//               overlapped with the h-gather / uE-copy blocks below
//   [+HB2)      h_all gather
//   [rest)      uEmbed copy
// iE-copy MUST precede ripple's scatter (write-write ordering) — that is the
// race that broke R10. Producers release via threadfence+atomic.
// Only 4KB static smem -> L1D carveout stays large for the rel table.
// ---------------------------------------------------------------------------
__global__ void __launch_bounds__(256) fused_kernel(
        const int*    __restrict__ pos,
        const int*    __restrict__ mh,
        const int*    __restrict__ mr,
        const int*    __restrict__ mt,
        const float*  __restrict__ W,
        const float4* __restrict__ uE4,
        const float4* __restrict__ iE4,
        const float4* __restrict__ ent4,
        const float4* __restrict__ rel4,
        float4* __restrict__ out_u4,
        float*  __restrict__ out_i,
        float4* __restrict__ out_h4,
        float4* __restrict__ out_t4,
        float4* __restrict__ out_r4,
        int HBM, int RB, int TB, int IB, int RP, int HB2,
        int Ue4, int Ie4, int BM, int B, int nhop, int target) {
    __shared__ float sW[DD * DD];          // 4KB only
    int blk = blockIdx.x;
    int tidx = threadIdx.x;
    const float* ent = (const float*)ent4;
    const float* iE  = (const float*)iE4;
    const unsigned FULL = 0xffffffffu;

    if (blk < RB) {
        // ---- r_all gather + Rh = R@h (register-only), hop0 -> logit0 ----
        int warp = tidx >> 5, lane = tidx & 31;
        int slot = blk * 8 + warp;
        if (slot < HBM) {
            int r = __ldg(&mr[slot]);
            const float4* src = rel4 + (size_t)r * 256;
            float4* dst = out_r4 + (size_t)slot * 256;

            float4 v[8];
            #pragma unroll
            for (int k = 0; k < 8; k++)
                v[k] = __ldg(&src[k * 32 + lane]);

            int e = __ldg(&mh[slot]);
            float hval = __ldg(&ent[(size_t)e * DD + lane]);

            int c4 = (lane & 7) * 4;
            float hx = __shfl_sync(FULL, hval, c4 + 0);
            float hy = __shfl_sync(FULL, hval, c4 + 1);
            float hz = __shfl_sync(FULL, hval, c4 + 2);
            float hw = __shfl_sync(FULL, hval, c4 + 3);

            float p[8];
            #pragma unroll
            for (int k = 0; k < 8; k++) {
                __stcs(&dst[k * 32 + lane], v[k]);
                p[k] = v[k].x * hx + v[k].y * hy + v[k].z * hz + v[k].w * hw;
            }
            #pragma unroll
            for (int k = 0; k < 8; k++) {
                p[k] += __shfl_xor_sync(FULL, p[k], 1);
                p[k] += __shfl_xor_sync(FULL, p[k], 2);
                p[k] += __shfl_xor_sync(FULL, p[k], 4);
            }
            int myk = lane & 7;
            float temp = p[0];
            #pragma unroll
            for (int k = 1; k < 8; k++) if (myk == k) temp = p[k];
            float acc = __shfl_sync(FULL, temp, ((lane & 3) << 3) + (lane >> 2));

            if (slot < BM) {
                int b = slot / MM;
                int p0 = __ldg(&pos[b]);
                float it0 = __ldg(&iE[(size_t)p0 * DD + lane]);
                float lg = warpSum(acc * it0);
                if (lane == 0) g_logit0[slot] = lg;
            } else {
                g_Rh[(size_t)slot * DD + lane] = acc;
            }
        }
        __threadfence();
        __syncthreads();
        if (tidx == 0) atomicAdd(&g_done, 1);
    } else if (blk < RB + TB) {
        // ---- t_all gather (ripple dependency) ----
        int tid = (blk - RB) * 256 + tidx;
        if (tid < HBM * 8) {
            int slot = tid >> 3, j = tid & 7;
            int e = __ldg(&mt[slot]);
            float4 v = __ldg(&ent4[(size_t)e * 8 + j]);
            v.x = v.x > 0.f ? v.x : LEAKY * v.x;
            v.y = v.y > 0.f ? v.y : LEAKY * v.y;
            v.z = v.z > 0.f ? v.z : LEAKY * v.z;
            v.w = v.w > 0.f ? v.w : LEAKY * v.w;
            out_t4[slot * 8 + j] = v;
        }
        __threadfence();
        __syncthreads();
        if (tidx == 0) atomicAdd(&g_done, 1);
    } else if (blk < RB + TB + IB) {
        // ---- iEmbed base copy (MUST complete before ripple's scatter) ----
        int j = (blk - RB - TB) * 256 + tidx;
        if (j < Ie4) {
            float4* out_i4 = (float4*)out_i;
            out_i4[j] = __ldg(&iE4[j]);
        }
        __threadfence();
        __syncthreads();
        if (tidx == 0) atomicAdd(&g_done, 1);
    } else if (blk < RB + TB + IB + RP) {
        // ---- ripple: spin-wait for producers, then hops + scatter ----
        for (int i = tidx; i < DD * DD; i += 256) sW[i] = __ldg(&W[i]);
        if (tidx == 0) {
            while (atomicAdd(&g_done, 0) < target) __nanosleep(128);
            __threadfence();
        }
        __syncthreads();

        int warp = tidx >> 5, lane = tidx & 31;
        int b = (blk - RB - TB - IB) * 8 + warp;
        if (b < B) {
            int p = __ldg(&pos[b]);
            bool dup = false;
            for (int j = b + 1 + lane; j < B; j += 32)
                dup |= (__ldg(&pos[j]) == p);
            if (!__any_sync(FULL, dup)) {
                float item = __ldg(&iE[(size_t)p * DD + lane]);
                for (int hop = 0; hop < nhop; hop++) {
                    float logit;
                    if (hop == 0) {
                        logit = __ldg(&g_logit0[(size_t)b * MM + lane]);
                    } else {
                        // register Rh@item (identical to validated Rh@h path)
                        const float4* Rh4 = (const float4*)
                            (g_Rh + (size_t)(hop * B + b) * MM * DD);
                        float4 v[8];
                        #pragma unroll
                        for (int k = 0; k < 8; k++)
                            v[k] = __ldg(&Rh4[k * 32 + lane]);
                        int c4 = (lane & 7) * 4;
                        float ix = __shfl_sync(FULL, item, c4 + 0);
                        float iy = __shfl_sync(FULL, item, c4 + 1);
                        float iz = __shfl_sync(FULL, item, c4 + 2);
                        float iw = __shfl_sync(FULL, item, c4 + 3);
                        float pq[8];
                        #pragma unroll
                        for (int k = 0; k < 8; k++)
                            pq[k] = v[k].x*ix + v[k].y*iy + v[k].z*iz + v[k].w*iw;
                        #pragma unroll
                        for (int k = 0; k < 8; k++) {
                            pq[k] += __shfl_xor_sync(FULL, pq[k], 1);
                            pq[k] += __shfl_xor_sync(FULL, pq[k], 2);
                            pq[k] += __shfl_xor_sync(FULL, pq[k], 4);
                        }
                        int myk = lane & 7;
                        float temp = pq[0];
                        #pragma unroll
                        for (int k = 1; k < 8; k++) if (myk == k) temp = pq[k];
                        logit = __shfl_sync(FULL, temp,
                                            ((lane & 3) << 3) + (lane >> 2));
                    }
                    float mx = warpMax(logit);
                    float ex = expf(logit - mx);
                    float prob = ex / warpSum(ex);

                    // o[d] = sum_m prob[m]*t[m][d] — validated R8 pattern
                    const float* tb =
                        ((const float*)out_t4) + (size_t)(hop * B + b) * MM * DD;
                    float o = 0.f;
                    #pragma unroll
                    for (int m = 0; m < MM; m++) {
                        float pm = __shfl_sync(FULL, prob, m);
                        o = fmaf(pm, __ldg(&tb[m * DD + lane]), o);
                    }

                    // item = (item + o) @ W.T (shuffle broadcast + smem W)
                    float x = item + o;
                    float ni = 0.f;
                    #pragma unroll
                    for (int e = 0; e < DD; e++) {
                        int ee = (e + lane) & (DD - 1);
                        ni = fmaf(__shfl_sync(FULL, x, ee),
                                  sW[lane * DD + ee], ni);
                    }
                    item = ni;
                }
                out_i[(size_t)p * DD + lane] = item;
            }
        }
        __syncthreads();
        if (tidx == 0) {
            int r = atomicAdd(&g_rdone, 1);
            if (r == RP - 1) { g_rdone = 0; g_done = 0; }   // replay reset
        }
    } else if (blk < RB + TB + IB + RP + HB2) {
        // ---- h_all gather (backfills ripple's spin) ----
        int tid = (blk - RB - TB - IB - RP) * 256 + tidx;
        if (tid < HBM * 8) {
            int slot = tid >> 3, j = tid & 7;
            int e = __ldg(&mh[slot]);
            __stcs(&out_h4[slot * 8 + j], __ldg(&ent4[(size_t)e * 8 + j]));
        }
    } else {
        // ---- uEmbed copy (backfills ripple's spin) ----
        int j = (blk - RB - TB - IB - RP - HB2) * 256 + tidx;
        if (j < Ue4)
            __stcs(&out_u4[j], __ldg(&uE4[j]));
    }
}

// ---------------------------------------------------------------------------
extern "C" void kernel_launch(void* const* d_in, const int* in_sizes, int n_in,
                              void* d_out, int out_size) {
    const int*   pos = (const int*)d_in[0];
    const int*   mh  = (const int*)d_in[1];
    const int*   mr  = (const int*)d_in[2];
    const int*   mt  = (const int*)d_in[3];
    const float* uE  = (const float*)d_in[4];
    const float* iE  = (const float*)d_in[5];
    const float* ent = (const float*)d_in[6];
    const float* rel = (const float*)d_in[7];
    const float* W   = (const float*)d_in[8];
    float* out = (float*)d_out;

    const int B    = in_sizes[0];             // 2048
    const int HBM  = in_sizes[1];             // H*B*M = 131072
    const int nhop = HBM / (B * MM);          // 2
    const int BM   = B * MM;                  // 65536
    const size_t Ue = (size_t)in_sizes[4];
    const size_t Ie = (size_t)in_sizes[5];

    float* out_u = out;
    float* out_i = out_u + Ue;
    float* out_h = out_i + Ie;
    float* out_t = out_h + (size_t)HBM * DD;
    float* out_r = out_t + (size_t)HBM * DD;

    const int RB  = (HBM + 7) / 8;                 // 16384
    const int TB  = (HBM * 8 + 255) / 256;         // 4096
    const int Ue4 = (int)(Ue / 4), Ie4 = (int)(Ie / 4);
    const int IB  = (Ie4 + 255) / 256;             // 3125
    const int RP  = (B + 7) / 8;                   // 256
    const int HB2 = (HBM * 8 + 255) / 256;         // 4096
    const int UB  = (Ue4 + 255) / 256;             // 3125
    const int target = RB + TB + IB;

    fused_kernel<<<RB + TB + IB + RP + HB2 + UB, 256>>>(
        pos, mh, mr, mt, W,
        (const float4*)uE, (const float4*)iE,
        (const float4*)ent, (const float4*)rel,
        (float4*)out_u, out_i, (float4*)out_h, (float4*)out_t, (float4*)out_r,
        HBM, RB, TB, IB, RP, HB2, Ue4, Ie4, BM, B, nhop, target);
}

// round 12
// speedup vs baseline: 1.4494x; 1.4494x over previous
#include <cuda_runtime.h>

#define DD    32          // embedding dim D
#define MM    32          // memories per hop
#define LEAKY 0.2f

// scratch: Rh[slot*D + d] for hop>=1 slots; hop-0 logits precomputed
__device__ float g_Rh[131072 * 32];
__device__ float g_logit0[131072];     // logit0[slot] for slot < B*M

__device__ __forceinline__ float warpSum(float v) {
    #pragma unroll
    for (int off = 16; off; off >>= 1) v += __shfl_xor_sync(0xffffffffu, v, off);
    return v;
}
__device__ __forceinline__ float warpMax(float v) {
    #pragma unroll
    for (int off = 16; off; off >>= 1) v = fmaxf(v, __shfl_xor_sync(0xffffffffu, v, off));
    return v;
}

// ---------------------------------------------------------------------------
// MEGA kernel (R9 version): blockIdx ranges select role.
//   [0, RB)          : r_all gather + fused Rh (warp-per-slot, 8 slots/block)
//                      hop-0 slots fold in item0 -> scalar logit0 (skip g_Rh)
//   [RB, RB+HB)      : h_all / t_all gather (float4 granularity)
//   [RB+HB, ...)     : uEmbed + iEmbed contiguous copy (float4)
// ZERO shared memory -> full 228KB L1D carveout -> rel table gets L1 hits.
// ---------------------------------------------------------------------------
__global__ void __launch_bounds__(256) mega_kernel(
        const int*    __restrict__ pos,
        const int*    __restrict__ mh,
        const int*    __restrict__ mr,
        const int*    __restrict__ mt,
        const float4* __restrict__ uE4,
        const float4* __restrict__ iE4,
        const float4* __restrict__ ent4,
        const float4* __restrict__ rel4,
        float4* __restrict__ out_u4,
        float4* __restrict__ out_h4,
        float4* __restrict__ out_t4,
        float4* __restrict__ out_r4,
        int HBM, int RB, int HB, int Ue4, int Ie4, int BM) {
    int blk = blockIdx.x;
    const float* ent = (const float*)ent4;
    const float* iE  = (const float*)iE4;
    const unsigned FULL = 0xffffffffu;

    if (blk < RB) {
        // ---- r_all gather + Rh = R@h, one warp per slot, register-only ----
        int warp = threadIdx.x >> 5, lane = threadIdx.x & 31;
        int slot = blk * 8 + warp;
        if (slot >= HBM) return;

        int r = __ldg(&mr[slot]);
        const float4* src = rel4 + (size_t)r * 256;
        float4* dst = out_r4 + (size_t)slot * 256;

        float4 v[8];
        #pragma unroll
        for (int k = 0; k < 8; k++)       // 8 outstanding loads (L1/L2)
            v[k] = __ldg(&src[k * 32 + lane]);

        int e = __ldg(&mh[slot]);
        float hval = __ldg(&ent[(size_t)e * DD + lane]);

        // h4 = h[4c..4c+3], c = lane&7  (v[k] covers R[4k+(lane>>3)][4c..4c+3])
        int c4 = (lane & 7) * 4;
        float hx = __shfl_sync(FULL, hval, c4 + 0);
        float hy = __shfl_sync(FULL, hval, c4 + 1);
        float hz = __shfl_sync(FULL, hval, c4 + 2);
        float hw = __shfl_sync(FULL, hval, c4 + 3);

        float p[8];
        #pragma unroll
        for (int k = 0; k < 8; k++) {
            __stcs(&dst[k * 32 + lane], v[k]);   // streaming write-out
            p[k] = v[k].x * hx + v[k].y * hy + v[k].z * hz + v[k].w * hw;
        }
        // reduce partials within each 8-lane group
        #pragma unroll
        for (int k = 0; k < 8; k++) {
            p[k] += __shfl_xor_sync(FULL, p[k], 1);
            p[k] += __shfl_xor_sync(FULL, p[k], 2);
            p[k] += __shfl_xor_sync(FULL, p[k], 4);
        }
        // permutation: lane d wants row d, held in p[d>>2] on lanes 8(d&3)+..
        int myk = lane & 7;
        float temp = p[0];
        #pragma unroll
        for (int k = 1; k < 8; k++) if (myk == k) temp = p[k];
        float acc = __shfl_sync(FULL, temp, ((lane & 3) << 3) + (lane >> 2));

        if (slot < BM) {
            // hop 0: fold in item0 = iE[pos[b]] -> scalar logit, skip g_Rh
            int b = slot / MM;
            int p0 = __ldg(&pos[b]);
            float it0 = __ldg(&iE[(size_t)p0 * DD + lane]);   // L1-hot row
            float lg = warpSum(acc * it0);
            if (lane == 0) g_logit0[slot] = lg;
        } else {
            g_Rh[(size_t)slot * DD + lane] = acc;
        }
    } else if (blk < RB + HB) {
        // ---- h_all / t_all gather ----
        int tid = (blk - RB) * 256 + threadIdx.x;
        int N = HBM * 8;                  // 8 float4 per 32-float row
        if (tid < N) {
            int slot = tid >> 3, j = tid & 7;
            int e = __ldg(&mh[slot]);
            __stcs(&out_h4[slot * 8 + j], __ldg(&ent4[(size_t)e * 8 + j]));
        } else if (tid < 2 * N) {
            int t2 = tid - N;
            int slot = t2 >> 3, j = t2 & 7;
            int e = __ldg(&mt[slot]);
            float4 v = __ldg(&ent4[(size_t)e * 8 + j]);
            v.x = v.x > 0.f ? v.x : LEAKY * v.x;
            v.y = v.y > 0.f ? v.y : LEAKY * v.y;
            v.z = v.z > 0.f ? v.z : LEAKY * v.z;
            v.w = v.w > 0.f ? v.w : LEAKY * v.w;
            out_t4[slot * 8 + j] = v;     // re-read by ripple: keep cacheable
        }
    } else {
        // ---- uEmbed + iEmbed copy (contiguous dst, never re-read) ----
        int j = (blk - RB - HB) * 256 + threadIdx.x;
        if (j < Ue4)
            __stcs(&out_u4[j], __ldg(&uE4[j]));
        else if (j < Ue4 + Ie4)
            __stcs(&out_u4[j], __ldg(&iE4[j - Ue4]));
    }
}

// ---------------------------------------------------------------------------
// Hop loop: one warp per batch row b, 8 warps/block. Hop 0 needs only the
// precomputed scalar logits, so hop 1's Rh tile is prefetched into smem AT
// WARP START and its latency is hidden behind hop 0's entire compute.
// Last-wins scatter resolved by inline duplicate scan over pos (L1-hot).
// ---------------------------------------------------------------------------
__global__ void __launch_bounds__(256) ripple_kernel(
        const int*   __restrict__ pos,
        const float* __restrict__ iE,
        const float* __restrict__ t_all,
        const float* __restrict__ W,
        float* __restrict__ out_i,
        int B, int nhop) {
    __shared__ float sW[DD * DD];
    __shared__ float sRh[8][DD * DD];   // 32KB: per-warp Rh tile (hop>=1)
    __shared__ float sIt[8][DD];
    for (int i = threadIdx.x; i < DD * DD; i += blockDim.x) sW[i] = W[i];
    __syncthreads();
    int warp = threadIdx.x >> 5, lane = threadIdx.x & 31;
    int b = blockIdx.x * 8 + warp;
    if (b >= B) return;
    int p = pos[b];

    // last-wins: if any later batch element maps to the same item, we lose.
    bool dup = false;
    for (int j = b + 1 + lane; j < B; j += 32) dup |= (pos[j] == p);
    if (__any_sync(0xffffffffu, dup)) return;

    float* myRh = sRh[warp];
    float* myIt = sIt[warp];

    // front-load: hop-1 Rh tile -> smem, logit0 -> reg, item -> reg.
    // 10 independent loads in flight before any compute.
    if (nhop > 1) {
        const float4* Rh4 = (const float4*)(g_Rh + (size_t)(B + b) * MM * DD);
        #pragma unroll
        for (int j = 0; j < 8; j++)
            ((float4*)myRh)[j * 32 + lane] = __ldg(&Rh4[j * 32 + lane]);
    }
    float logit = __ldg(&g_logit0[(size_t)b * MM + lane]);
    float item = __ldg(&iE[(size_t)p * DD + lane]);

    for (int hop = 0; hop < nhop; hop++) {
        if (hop > 0) {
            if (hop > 1) {   // generic fallback for nhop>2 (unused @nhop=2)
                const float4* Rh4 =
                    (const float4*)(g_Rh + (size_t)(hop * B + b) * MM * DD);
                #pragma unroll
                for (int j = 0; j < 8; j++)
                    ((float4*)myRh)[j * 32 + lane] = __ldg(&Rh4[j * 32 + lane]);
            }
            myIt[lane] = item;
            __syncwarp();
            // logit[m] on lane m: independent FMAs, conflict-free rotation
            logit = 0.f;
            #pragma unroll
            for (int i = 0; i < DD; i++) {
                int ee = (i + lane) & (DD - 1);
                logit = fmaf(myRh[lane * DD + ee], myIt[ee], logit);
            }
        }
        // softmax across lanes
        float mx = warpMax(logit);
        float ex = expf(logit - mx);
        float prob = ex / warpSum(ex);
        // o[d] = sum_m prob[m] * t[m][d]  (coalesced L2-hot loads)
        const float* tb = t_all + (size_t)(hop * B + b) * MM * DD;
        float o = 0.f;
        #pragma unroll
        for (int m = 0; m < MM; m++) {
            float pm = __shfl_sync(0xffffffffu, prob, m);
            o = fmaf(pm, __ldg(&tb[m * DD + lane]), o);
        }
        // item = (item + o) @ W.T via smem broadcast
        __syncwarp();
        myIt[lane] = item + o;
        __syncwarp();
        float ni = 0.f;
        #pragma unroll
        for (int e = 0; e < DD; e++) {
            int ee = (e + lane) & (DD - 1);
            ni = fmaf(myIt[ee], sW[lane * DD + ee], ni);
        }
        item = ni;
        __syncwarp();
    }
    out_i[(size_t)p * DD + lane] = item;
}

// ---------------------------------------------------------------------------
extern "C" void kernel_launch(void* const* d_in, const int* in_sizes, int n_in,
                              void* d_out, int out_size) {
    const int*   pos = (const int*)d_in[0];
    const int*   mh  = (const int*)d_in[1];
    const int*   mr  = (const int*)d_in[2];
    const int*   mt  = (const int*)d_in[3];
    const float* uE  = (const float*)d_in[4];
    const float* iE  = (const float*)d_in[5];
    const float* ent = (const float*)d_in[6];
    const float* rel = (const float*)d_in[7];
    const float* W   = (const float*)d_in[8];
    float* out = (float*)d_out;

    const int B    = in_sizes[0];             // 2048
    const int HBM  = in_sizes[1];             // H*B*M = 131072
    const int nhop = HBM / (B * MM);          // 2
    const int BM   = B * MM;                  // 65536
    const size_t Ue = (size_t)in_sizes[4];    // USER*D floats
    const size_t Ie = (size_t)in_sizes[5];    // ITEM*D floats

    float* out_u = out;
    float* out_i = out_u + Ue;
    float* out_h = out_i + Ie;
    float* out_t = out_h + (size_t)HBM * DD;
    float* out_r = out_t + (size_t)HBM * DD;

    const int RB  = (HBM + 7) / 8;                      // 16384 r-blocks
    const int HB  = (2 * HBM * 8 + 255) / 256;          // 8192 ht-blocks
    const int Ue4 = (int)(Ue / 4), Ie4 = (int)(Ie / 4);
    const int CB  = (Ue4 + Ie4 + 255) / 256;            // 6250 copy-blocks

    mega_kernel<<<RB + HB + CB, 256>>>(
        pos, mh, mr, mt,
        (const float4*)uE, (const float4*)iE,
        (const float4*)ent, (const float4*)rel,
        (float4*)out_u, (float4*)out_h, (float4*)out_t, (float4*)out_r,
        HBM, RB, HB, Ue4, Ie4, BM);

    ripple_kernel<<<(B + 7) / 8, 256>>>(pos, iE, out_t, W, out_i, B, nhop);
}